// round 8
// baseline (speedup 1.0000x reference)
#include <cuda_runtime.h>

#define IMG   1024
#define HWSZ  (IMG*IMG)
#define NB    16
#define W     128          // padded tile width = 32 lanes * 4
#define INTW  112          // interior width (halo 8 each side)
#define NW    16           // warps per block
#define RPT   6            // rows per thread
#define H     (NW*RPT)     // 96 padded rows
#define INTH  80           // interior rows
#define NTH   512
#define SENT  1e30f
#define NEGS  (-1e30f)

// ping-pong eroded-image scratch (static device arrays: allowed)
__device__ float g_e0[(size_t)NB * HWSZ];
__device__ float g_e1[(size_t)NB * HWSZ];

struct Edges {
    float4 eT[NW][32];   // each warp's top e-row
    float4 eB[NW][32];   // bottom e-row
    float4 hT[NW][32];   // top hmax-row
    float4 hB[NW][32];   // bottom hmax-row
};

__device__ __forceinline__ float4 f4s() { return make_float4(SENT, SENT, SENT, SENT); }
__device__ __forceinline__ float4 f4n() { return make_float4(NEGS, NEGS, NEGS, NEGS); }

__device__ __forceinline__ float4 f4min5(float4 ce, float4 up, float4 dn, float lf, float rt) {
    float4 o;
    o.x = fminf(fminf(ce.x, fminf(up.x, dn.x)), fminf(lf,   ce.y));
    o.y = fminf(fminf(ce.y, fminf(up.y, dn.y)), fminf(ce.x, ce.z));
    o.z = fminf(fminf(ce.z, fminf(up.z, dn.z)), fminf(ce.y, ce.w));
    o.w = fminf(fminf(ce.w, fminf(up.w, dn.w)), fminf(ce.z, rt));
    return o;
}

__device__ __forceinline__ float dv(float v) { return v > 1e29f ? NEGS : v; }
__device__ __forceinline__ float4 dv4(float4 v) {
    return make_float4(dv(v.x), dv(v.y), dv(v.z), dv(v.w));
}

__device__ __forceinline__ float4 hmax4(float4 ce, float lf, float rt) {
    float m01 = fmaxf(ce.x, ce.y), m23 = fmaxf(ce.z, ce.w);
    float4 h;
    h.x = fmaxf(lf,   m01);
    h.y = fmaxf(m01,  ce.z);
    h.z = fmaxf(ce.y, m23);
    h.w = fmaxf(m23,  rt);
    return h;
}

// horizontal 3-max of one register row, neighbors via warp shuffle.
// Non-BDRY: lane-edge values are shuffle self-copies (ring-0..3 garbage, provably
// outside the exactness cone). BDRY: exact sentinel handling via dv().
template<bool BDRY>
__device__ __forceinline__ float4 hrow(float4 v, int l) {
    float lf = __shfl_up_sync(0xffffffffu, v.w, 1);
    float rt = __shfl_down_sync(0xffffffffu, v.x, 1);
    if (BDRY) {
        if (l == 0)  lf = SENT;
        if (l == 31) rt = SENT;
        return hmax4(dv4(v), dv(lf), dv(rt));
    }
    return hmax4(v, lf, rt);
}

template<bool BDRY>
__device__ __forceinline__ void run_steps(
    int nsteps, Edges* eb, float4 (&e)[RPT], float4 (&skr)[RPT],
    int l, int w, int gc0, int orow, int r0)
{
    bool rowbad[RPT];
    bool cb0 = false, cb1 = false, cb2 = false, cb3 = false;
    if (BDRY) {
#pragma unroll
        for (int r = 0; r < RPT; ++r)
            rowbad[r] = (unsigned)(orow + r0 + r) >= IMG;
        cb0 = (unsigned)(gc0 + 0) >= IMG;
        cb1 = (unsigned)(gc0 + 1) >= IMG;
        cb2 = (unsigned)(gc0 + 2) >= IMG;
        cb3 = (unsigned)(gc0 + 3) >= IMG;
    }

    for (int step = 0; step < nsteps; ++step) {
        Edges* rd = &eb[step & 1];
        Edges* wr = &eb[(step & 1) ^ 1];

        // ---- erode: up/down via smem warp edges, left/right via shuffle ----
        float4 up = (w > 0)      ? rd->eB[w - 1][l] : f4s();
        float4 dn = (w < NW - 1) ? rd->eT[w + 1][l] : f4s();

        float4 n[RPT];
#pragma unroll
        for (int r = 0; r < RPT; ++r) {
            float lf = __shfl_up_sync(0xffffffffu, e[r].w, 1);
            float rt = __shfl_down_sync(0xffffffffu, e[r].x, 1);
            if (BDRY) {
                if (l == 0)  lf = SENT;
                if (l == 31) rt = SENT;
            }
            float4 u = (r == 0)       ? up : e[r - 1];
            float4 d = (r == RPT - 1) ? dn : e[r + 1];
            n[r] = f4min5(e[r], u, d, lf, rt);
        }

        if (BDRY) {
            // re-impose +inf sentinel at out-of-image cells (exact erode semantics)
#pragma unroll
            for (int r = 0; r < RPT; ++r) {
                if (rowbad[r]) n[r] = f4s();
                else {
                    if (cb0) n[r].x = SENT;
                    if (cb1) n[r].y = SENT;
                    if (cb2) n[r].z = SENT;
                    if (cb3) n[r].w = SENT;
                }
            }
        }

        // ---- publish new e edges + boundary hmax rows ----
        float4 hm0, hm5;
        wr->eT[w][l] = n[0];
        wr->eB[w][l] = n[RPT - 1];
        if (w != 0) {                    // hT consumed as hD by warp w-1
            hm0 = hrow<BDRY>(n[0], l);
            wr->hT[w][l] = hm0;
        }
        if (w != NW - 1) {               // hB consumed as hU by warp w+1
            hm5 = hrow<BDRY>(n[RPT - 1], l);
            wr->hB[w][l] = hm5;
        }
        __syncthreads();

        // ---- dilate (rolling vertical 3-max) + delta + sk: interior warps only ----
        if (w != 0 && w != NW - 1) {
            float4 hU = wr->hB[w - 1][l];
            float4 hD = wr->hT[w + 1][l];

            float4 hA = hU, hB = hm0;
#pragma unroll
            for (int r = 0; r < RPT; ++r) {
                float4 hC;
                if (r == RPT - 2)      hC = hm5;
                else if (r == RPT - 1) hC = hD;
                else                   hC = hrow<BDRY>(n[r + 1], l);

                float vx = fmaxf(hB.x, fmaxf(hA.x, hC.x));
                float vy = fmaxf(hB.y, fmaxf(hA.y, hC.y));
                float vz = fmaxf(hB.z, fmaxf(hA.z, hC.z));
                float vw = fmaxf(hB.w, fmaxf(hA.w, hC.w));

                float dx = fmaxf(e[r].x - vx, 0.f);
                float dy = fmaxf(e[r].y - vy, 0.f);
                float dz = fmaxf(e[r].z - vz, 0.f);
                float dw = fmaxf(e[r].w - vw, 0.f);

                // sk += d - sk*d  (relu dropped: argument >= -O(ulp), fma-pipe form)
                skr[r].x = __fmaf_rn(-skr[r].x, dx, skr[r].x + dx);
                skr[r].y = __fmaf_rn(-skr[r].y, dy, skr[r].y + dy);
                skr[r].z = __fmaf_rn(-skr[r].z, dz, skr[r].z + dz);
                skr[r].w = __fmaf_rn(-skr[r].w, dw, skr[r].w + dw);

                hA = hB; hB = hC;
                e[r] = n[r];
            }
        } else {
#pragma unroll
            for (int r = 0; r < RPT; ++r) e[r] = n[r];
        }
        // one barrier per step: parity double-buffering removes the WAR hazard
    }
}

__global__ void __launch_bounds__(NTH, 1)
skel_kernel(const float* __restrict__ img, float* __restrict__ sk,
            int insel, int outsel, int nsteps, int first)
{
    extern __shared__ Edges eb[];   // eb[2], 64 KB

    const float* ein  = (insel == 0) ? img : (insel == 1 ? g_e0 : g_e1);
    float*       eout = (outsel == 1) ? g_e0 : g_e1;

    const int b = blockIdx.z;
    int tx0 = blockIdx.x * INTW;
    if (tx0 > IMG - INTW) tx0 = IMG - INTW;     // clamped overlap tile (idempotent)
    int ty0 = blockIdx.y * INTH;
    if (ty0 > IMG - INTH) ty0 = IMG - INTH;
    const int ocol = tx0 - 8, orow = ty0 - 8;

    const int t = threadIdx.x;
    const int l = t & 31, w = t >> 5;
    const int r0 = w * RPT;
    const int gc0 = ocol + 4 * l;

    const float* inb = ein  + (size_t)b * HWSZ;
    float*       skb = sk   + (size_t)b * HWSZ;
    float*       eob = eout + (size_t)b * HWSZ;

    const bool bdry = (orow < 0) | (orow + H > IMG) | (ocol < 0) | (ocol + W > IMG);

    // ---- load tile block into registers ----
    float4 e[RPT];
    if (!bdry) {
#pragma unroll
        for (int r = 0; r < RPT; ++r)
            e[r] = *(const float4*)(inb + (size_t)(orow + r0 + r) * IMG + gc0);
    } else {
#pragma unroll
        for (int r = 0; r < RPT; ++r) {
            int gr = orow + r0 + r;
            bool rok = (unsigned)gr < IMG;
            const float* row = inb + (size_t)(rok ? gr : 0) * IMG;
            float4 v;
            v.x = (rok && (unsigned)(gc0 + 0) < IMG) ? row[gc0 + 0] : SENT;
            v.y = (rok && (unsigned)(gc0 + 1) < IMG) ? row[gc0 + 1] : SENT;
            v.z = (rok && (unsigned)(gc0 + 2) < IMG) ? row[gc0 + 2] : SENT;
            v.w = (rok && (unsigned)(gc0 + 3) < IMG) ? row[gc0 + 3] : SENT;
            e[r] = v;
        }
    }

    // ---- sk accumulators (interior: lanes 2..29, rows 8..87) ----
    const bool xint = (l >= 2) && (l < 30);
    float4 skr[RPT];
#pragma unroll
    for (int r = 0; r < RPT; ++r) {
        int q = r0 + r;
        if (!first && xint && q >= 8 && q < 8 + INTH)
            skr[r] = *(const float4*)(skb + (size_t)(ty0 + q - 8) * IMG + (tx0 + 4 * (l - 2)));
        else
            skr[r] = make_float4(0.f, 0.f, 0.f, 0.f);
    }

    // ---- publish e_0 edges into parity 0 ----
    eb[0].eT[w][l] = e[0];
    eb[0].eB[w][l] = e[RPT - 1];
    __syncthreads();

    if (bdry) run_steps<true >(nsteps, eb, e, skr, l, w, gc0, orow, r0);
    else      run_steps<false>(nsteps, eb, e, skr, l, w, gc0, orow, r0);

    // ---- write sk and final eroded image (interior 112x80) ----
    if (xint) {
#pragma unroll
        for (int r = 0; r < RPT; ++r) {
            int q = r0 + r;
            if (q >= 8 && q < 8 + INTH) {
                size_t g = (size_t)(ty0 + q - 8) * IMG + (tx0 + 4 * (l - 2));
                *(float4*)(skb + g) = skr[r];
                *(float4*)(eob + g) = e[r];
            }
        }
    }
}

extern "C" void kernel_launch(void* const* d_in, const int* in_sizes, int n_in,
                              void* d_out, int out_size)
{
    const float* img = (const float*)d_in[0];
    float* sk = (float*)d_out;

    const int smem = 2 * (int)sizeof(Edges);   // 65536 bytes
    cudaFuncSetAttribute(skel_kernel,
                         cudaFuncAttributeMaxDynamicSharedMemorySize, smem);

    dim3 grid((IMG + INTW - 1) / INTW, (IMG + INTH - 1) / INTH, NB);  // 10 x 13 x 16
    dim3 block(NTH);

    // 6 launches: 7+7+7+7+7+6 = 41 deltas (e_0 .. e_41)
    skel_kernel<<<grid, block, smem>>>(img, sk, 0, 1, 7, 1);
    skel_kernel<<<grid, block, smem>>>(img, sk, 1, 2, 7, 0);
    skel_kernel<<<grid, block, smem>>>(img, sk, 2, 1, 7, 0);
    skel_kernel<<<grid, block, smem>>>(img, sk, 1, 2, 7, 0);
    skel_kernel<<<grid, block, smem>>>(img, sk, 2, 1, 7, 0);
    skel_kernel<<<grid, block, smem>>>(img, sk, 1, 2, 6, 0);
}

// round 9
// speedup vs baseline: 1.0616x; 1.0616x over previous
#include <cuda_runtime.h>

#define IMG   1024
#define HWSZ  (IMG*IMG)
#define NB    16
#define W     128          // padded tile width = 32 lanes * 4
#define INTW  112          // interior width (halo 8 each side)
#define NW    16           // warps per block
#define RPT   6            // rows per thread
#define H     (NW*RPT)     // 96 padded rows
#define INTH  80           // interior rows
#define NTH   512
#define SENT  1e30f
#define NEGS  (-1e30f)

// pairwise named barrier between two adjacent warps (64 threads)
#define BARP(id) asm volatile("bar.sync %0, 64;" :: "r"(id) : "memory")

// ping-pong eroded-image scratch (static device arrays: allowed)
__device__ float g_e0[(size_t)NB * HWSZ];
__device__ float g_e1[(size_t)NB * HWSZ];

struct Edges {
    float4 eT[NW][32];   // each warp's top e-row
    float4 eB[NW][32];   // bottom e-row
    float4 hT[NW][32];   // top hmax-row
    float4 hB[NW][32];   // bottom hmax-row
};

__device__ __forceinline__ float4 f4s() { return make_float4(SENT, SENT, SENT, SENT); }

__device__ __forceinline__ float4 f4min5(float4 ce, float4 up, float4 dn, float lf, float rt) {
    float4 o;
    o.x = fminf(fminf(ce.x, fminf(up.x, dn.x)), fminf(lf,   ce.y));
    o.y = fminf(fminf(ce.y, fminf(up.y, dn.y)), fminf(ce.x, ce.z));
    o.z = fminf(fminf(ce.z, fminf(up.z, dn.z)), fminf(ce.y, ce.w));
    o.w = fminf(fminf(ce.w, fminf(up.w, dn.w)), fminf(ce.z, rt));
    return o;
}

__device__ __forceinline__ float dv(float v) { return v > 1e29f ? NEGS : v; }
__device__ __forceinline__ float4 dv4(float4 v) {
    return make_float4(dv(v.x), dv(v.y), dv(v.z), dv(v.w));
}

__device__ __forceinline__ float4 hmax4(float4 ce, float lf, float rt) {
    float m01 = fmaxf(ce.x, ce.y), m23 = fmaxf(ce.z, ce.w);
    float4 h;
    h.x = fmaxf(lf,   m01);
    h.y = fmaxf(m01,  ce.z);
    h.z = fmaxf(ce.y, m23);
    h.w = fmaxf(m23,  rt);
    return h;
}

// horizontal 3-max of one register row, neighbors via warp shuffle.
// Non-BDRY: lane-edge values are shuffle self-copies (ring-0..3 garbage, provably
// outside the exactness cone). BDRY: exact sentinel handling via dv().
template<bool BDRY>
__device__ __forceinline__ float4 hrow(float4 v, int l) {
    float lf = __shfl_up_sync(0xffffffffu, v.w, 1);
    float rt = __shfl_down_sync(0xffffffffu, v.x, 1);
    if (BDRY) {
        if (l == 0)  lf = SENT;
        if (l == 31) rt = SENT;
        return hmax4(dv4(v), dv(lf), dv(rt));
    }
    return hmax4(v, lf, rt);
}

template<bool BDRY>
__device__ __forceinline__ void run_steps(
    int nsteps, Edges* eb, float4 (&e)[RPT], float4 (&skr)[RPT],
    int l, int w, int gc0, int orow, int r0)
{
    bool rowbad[RPT];
    bool cb0 = false, cb1 = false, cb2 = false, cb3 = false;
    if (BDRY) {
#pragma unroll
        for (int r = 0; r < RPT; ++r)
            rowbad[r] = (unsigned)(orow + r0 + r) >= IMG;
        cb0 = (unsigned)(gc0 + 0) >= IMG;
        cb1 = (unsigned)(gc0 + 1) >= IMG;
        cb2 = (unsigned)(gc0 + 2) >= IMG;
        cb3 = (unsigned)(gc0 + 3) >= IMG;
    }

    for (int step = 0; step < nsteps; ++step) {
        Edges* rd = &eb[step & 1];
        Edges* wr = &eb[(step & 1) ^ 1];

        // ---- erode: up/down via smem warp edges, left/right via shuffle ----
        float4 up = (w > 0)      ? rd->eB[w - 1][l] : f4s();
        float4 dn = (w < NW - 1) ? rd->eT[w + 1][l] : f4s();

        float4 n[RPT];
#pragma unroll
        for (int r = 0; r < RPT; ++r) {
            float lf = __shfl_up_sync(0xffffffffu, e[r].w, 1);
            float rt = __shfl_down_sync(0xffffffffu, e[r].x, 1);
            if (BDRY) {
                if (l == 0)  lf = SENT;
                if (l == 31) rt = SENT;
            }
            float4 u = (r == 0)       ? up : e[r - 1];
            float4 d = (r == RPT - 1) ? dn : e[r + 1];
            n[r] = f4min5(e[r], u, d, lf, rt);
        }

        if (BDRY) {
            // re-impose +inf sentinel at out-of-image cells (exact erode semantics)
#pragma unroll
            for (int r = 0; r < RPT; ++r) {
                if (rowbad[r]) n[r] = f4s();
                else {
                    if (cb0) n[r].x = SENT;
                    if (cb1) n[r].y = SENT;
                    if (cb2) n[r].z = SENT;
                    if (cb3) n[r].w = SENT;
                }
            }
        }

        // ---- publish new e edges + boundary hmax rows ----
        float4 hm0, hm5;
        wr->eT[w][l] = n[0];
        wr->eB[w][l] = n[RPT - 1];
        if (w != 0) {                    // hT consumed as hD by warp w-1
            hm0 = hrow<BDRY>(n[0], l);
            wr->hT[w][l] = hm0;
        }
        if (w != NW - 1) {               // hB consumed as hU by warp w+1
            hm5 = hrow<BDRY>(n[RPT - 1], l);
            wr->hB[w][l] = hm5;
        }

        // ---- pairwise neighbor sync (lower barrier id first: no deadlock) ----
        if (w > 0)      BARP(w);
        if (w < NW - 1) BARP(w + 1);

        // ---- dilate (rolling vertical 3-max) + delta + sk: interior warps only ----
        if (w != 0 && w != NW - 1) {
            float4 hU = wr->hB[w - 1][l];
            float4 hD = wr->hT[w + 1][l];

            float4 hA = hU, hB = hm0;
#pragma unroll
            for (int r = 0; r < RPT; ++r) {
                float4 hC;
                if (r == RPT - 2)      hC = hm5;
                else if (r == RPT - 1) hC = hD;
                else                   hC = hrow<BDRY>(n[r + 1], l);

                float vx = fmaxf(hB.x, fmaxf(hA.x, hC.x));
                float vy = fmaxf(hB.y, fmaxf(hA.y, hC.y));
                float vz = fmaxf(hB.z, fmaxf(hA.z, hC.z));
                float vw = fmaxf(hB.w, fmaxf(hA.w, hC.w));

                float dx = fmaxf(e[r].x - vx, 0.f);
                float dy = fmaxf(e[r].y - vy, 0.f);
                float dz = fmaxf(e[r].z - vz, 0.f);
                float dw = fmaxf(e[r].w - vw, 0.f);

                // sk += d - sk*d  (relu dropped: argument >= -O(ulp), fma-pipe form)
                skr[r].x = __fmaf_rn(-skr[r].x, dx, skr[r].x + dx);
                skr[r].y = __fmaf_rn(-skr[r].y, dy, skr[r].y + dy);
                skr[r].z = __fmaf_rn(-skr[r].z, dz, skr[r].z + dz);
                skr[r].w = __fmaf_rn(-skr[r].w, dw, skr[r].w + dw);

                hA = hB; hB = hC;
                e[r] = n[r];
            }
        } else {
#pragma unroll
            for (int r = 0; r < RPT; ++r) e[r] = n[r];
        }
        // parity double-buffering + pairwise happens-before chain removes WAR hazards
    }
}

__global__ void __launch_bounds__(NTH, 1)
skel_kernel(const float* __restrict__ img, float* __restrict__ sk,
            int insel, int outsel, int nsteps, int first)
{
    extern __shared__ Edges eb[];   // eb[2], 64 KB

    const float* ein  = (insel == 0) ? img : (insel == 1 ? g_e0 : g_e1);
    float*       eout = (outsel == 1) ? g_e0 : g_e1;

    const int b = blockIdx.z;
    int tx0 = blockIdx.x * INTW;
    if (tx0 > IMG - INTW) tx0 = IMG - INTW;     // clamped overlap tile (idempotent)
    int ty0 = blockIdx.y * INTH;
    if (ty0 > IMG - INTH) ty0 = IMG - INTH;
    const int ocol = tx0 - 8, orow = ty0 - 8;

    const int t = threadIdx.x;
    const int l = t & 31, w = t >> 5;
    const int r0 = w * RPT;
    const int gc0 = ocol + 4 * l;

    const float* inb = ein  + (size_t)b * HWSZ;
    float*       skb = sk   + (size_t)b * HWSZ;
    float*       eob = eout + (size_t)b * HWSZ;

    const bool bdry = (orow < 0) | (orow + H > IMG) | (ocol < 0) | (ocol + W > IMG);

    // ---- load tile block into registers ----
    float4 e[RPT];
    if (!bdry) {
#pragma unroll
        for (int r = 0; r < RPT; ++r)
            e[r] = *(const float4*)(inb + (size_t)(orow + r0 + r) * IMG + gc0);
    } else {
#pragma unroll
        for (int r = 0; r < RPT; ++r) {
            int gr = orow + r0 + r;
            bool rok = (unsigned)gr < IMG;
            const float* row = inb + (size_t)(rok ? gr : 0) * IMG;
            float4 v;
            v.x = (rok && (unsigned)(gc0 + 0) < IMG) ? row[gc0 + 0] : SENT;
            v.y = (rok && (unsigned)(gc0 + 1) < IMG) ? row[gc0 + 1] : SENT;
            v.z = (rok && (unsigned)(gc0 + 2) < IMG) ? row[gc0 + 2] : SENT;
            v.w = (rok && (unsigned)(gc0 + 3) < IMG) ? row[gc0 + 3] : SENT;
            e[r] = v;
        }
    }

    // ---- sk accumulators (interior: lanes 2..29, rows 8..87) ----
    const bool xint = (l >= 2) && (l < 30);
    float4 skr[RPT];
#pragma unroll
    for (int r = 0; r < RPT; ++r) {
        int q = r0 + r;
        if (!first && xint && q >= 8 && q < 8 + INTH)
            skr[r] = *(const float4*)(skb + (size_t)(ty0 + q - 8) * IMG + (tx0 + 4 * (l - 2)));
        else
            skr[r] = make_float4(0.f, 0.f, 0.f, 0.f);
    }

    // ---- publish e_0 edges into parity 0 ----
    eb[0].eT[w][l] = e[0];
    eb[0].eB[w][l] = e[RPT - 1];
    __syncthreads();

    if (bdry) run_steps<true >(nsteps, eb, e, skr, l, w, gc0, orow, r0);
    else      run_steps<false>(nsteps, eb, e, skr, l, w, gc0, orow, r0);

    // ---- write sk and final eroded image (interior 112x80) ----
    if (xint) {
#pragma unroll
        for (int r = 0; r < RPT; ++r) {
            int q = r0 + r;
            if (q >= 8 && q < 8 + INTH) {
                size_t g = (size_t)(ty0 + q - 8) * IMG + (tx0 + 4 * (l - 2));
                *(float4*)(skb + g) = skr[r];
                *(float4*)(eob + g) = e[r];
            }
        }
    }
}

extern "C" void kernel_launch(void* const* d_in, const int* in_sizes, int n_in,
                              void* d_out, int out_size)
{
    const float* img = (const float*)d_in[0];
    float* sk = (float*)d_out;

    const int smem = 2 * (int)sizeof(Edges);   // 65536 bytes
    cudaFuncSetAttribute(skel_kernel,
                         cudaFuncAttributeMaxDynamicSharedMemorySize, smem);

    dim3 grid((IMG + INTW - 1) / INTW, (IMG + INTH - 1) / INTH, NB);  // 10 x 13 x 16
    dim3 block(NTH);

    // 6 launches: 7+7+7+7+7+6 = 41 deltas (e_0 .. e_41)
    skel_kernel<<<grid, block, smem>>>(img, sk, 0, 1, 7, 1);
    skel_kernel<<<grid, block, smem>>>(img, sk, 1, 2, 7, 0);
    skel_kernel<<<grid, block, smem>>>(img, sk, 2, 1, 7, 0);
    skel_kernel<<<grid, block, smem>>>(img, sk, 1, 2, 7, 0);
    skel_kernel<<<grid, block, smem>>>(img, sk, 2, 1, 7, 0);
    skel_kernel<<<grid, block, smem>>>(img, sk, 1, 2, 6, 0);
}

// round 10
// speedup vs baseline: 1.0910x; 1.0277x over previous
#include <cuda_runtime.h>

#define IMG   1024
#define HWSZ  (IMG*IMG)
#define NB    16
#define W     128          // padded tile width = 32 lanes * 4
#define INTW  112          // interior width (halo 8 each side)
#define NW    8            // warps per block
#define RPT   6            // rows per thread
#define H     (NW*RPT)     // 48 padded rows
#define INTH  32           // interior rows
#define NTH   256
#define SENT  1e30f
#define NEGS  (-1e30f)

// pairwise named barrier between two adjacent warps (64 threads)
#define BARP(id) asm volatile("bar.sync %0, 64;" :: "r"(id) : "memory")

// ping-pong eroded-image scratch (static device arrays: allowed)
__device__ float g_e0[(size_t)NB * HWSZ];
__device__ float g_e1[(size_t)NB * HWSZ];

struct Edges {
    float4 eT[NW][32];   // each warp's top e-row
    float4 eB[NW][32];   // bottom e-row
    float4 hT[NW][32];   // top hmax-row
    float4 hB[NW][32];   // bottom hmax-row
};

__device__ __forceinline__ float4 f4s() { return make_float4(SENT, SENT, SENT, SENT); }

__device__ __forceinline__ float4 f4min5(float4 ce, float4 up, float4 dn, float lf, float rt) {
    float4 o;
    o.x = fminf(fminf(ce.x, fminf(up.x, dn.x)), fminf(lf,   ce.y));
    o.y = fminf(fminf(ce.y, fminf(up.y, dn.y)), fminf(ce.x, ce.z));
    o.z = fminf(fminf(ce.z, fminf(up.z, dn.z)), fminf(ce.y, ce.w));
    o.w = fminf(fminf(ce.w, fminf(up.w, dn.w)), fminf(ce.z, rt));
    return o;
}

__device__ __forceinline__ float dv(float v) { return v > 1e29f ? NEGS : v; }
__device__ __forceinline__ float4 dv4(float4 v) {
    return make_float4(dv(v.x), dv(v.y), dv(v.z), dv(v.w));
}

__device__ __forceinline__ float4 hmax4(float4 ce, float lf, float rt) {
    float m01 = fmaxf(ce.x, ce.y), m23 = fmaxf(ce.z, ce.w);
    float4 h;
    h.x = fmaxf(lf,   m01);
    h.y = fmaxf(m01,  ce.z);
    h.z = fmaxf(ce.y, m23);
    h.w = fmaxf(m23,  rt);
    return h;
}

// horizontal 3-max of one register row, neighbors via warp shuffle.
// Non-BDRY: lane-edge values are shuffle self-copies (ring-0..3 garbage, provably
// outside the exactness cone). BDRY: exact sentinel handling via dv().
template<bool BDRY>
__device__ __forceinline__ float4 hrow(float4 v, int l) {
    float lf = __shfl_up_sync(0xffffffffu, v.w, 1);
    float rt = __shfl_down_sync(0xffffffffu, v.x, 1);
    if (BDRY) {
        if (l == 0)  lf = SENT;
        if (l == 31) rt = SENT;
        return hmax4(dv4(v), dv(lf), dv(rt));
    }
    return hmax4(v, lf, rt);
}

template<bool BDRY, int NSTEPS>
__device__ __forceinline__ void run_steps(
    Edges* eb, float4 (&e)[RPT], float4 (&skr)[RPT],
    int l, int w, int gc0, int orow, int r0)
{
    bool rowbad[RPT];
    bool cb0 = false, cb1 = false, cb2 = false, cb3 = false;
    if (BDRY) {
#pragma unroll
        for (int r = 0; r < RPT; ++r)
            rowbad[r] = (unsigned)(orow + r0 + r) >= IMG;
        cb0 = (unsigned)(gc0 + 0) >= IMG;
        cb1 = (unsigned)(gc0 + 1) >= IMG;
        cb2 = (unsigned)(gc0 + 2) >= IMG;
        cb3 = (unsigned)(gc0 + 3) >= IMG;
    }

#pragma unroll
    for (int step = 0; step < NSTEPS; ++step) {
        Edges* rd = &eb[step & 1];
        Edges* wr = &eb[(step & 1) ^ 1];

        // ---- erode: up/down via smem warp edges, left/right via shuffle ----
        float4 up = (w > 0)      ? rd->eB[w - 1][l] : f4s();
        float4 dn = (w < NW - 1) ? rd->eT[w + 1][l] : f4s();

        float4 n[RPT];
#pragma unroll
        for (int r = 0; r < RPT; ++r) {
            float lf = __shfl_up_sync(0xffffffffu, e[r].w, 1);
            float rt = __shfl_down_sync(0xffffffffu, e[r].x, 1);
            if (BDRY) {
                if (l == 0)  lf = SENT;
                if (l == 31) rt = SENT;
            }
            float4 u = (r == 0)       ? up : e[r - 1];
            float4 d = (r == RPT - 1) ? dn : e[r + 1];
            n[r] = f4min5(e[r], u, d, lf, rt);
        }

        if (BDRY) {
            // re-impose +inf sentinel at out-of-image cells (exact erode semantics)
#pragma unroll
            for (int r = 0; r < RPT; ++r) {
                if (rowbad[r]) n[r] = f4s();
                else {
                    if (cb0) n[r].x = SENT;
                    if (cb1) n[r].y = SENT;
                    if (cb2) n[r].z = SENT;
                    if (cb3) n[r].w = SENT;
                }
            }
        }

        // ---- publish new e edges + boundary hmax rows ----
        float4 hm0, hm5;
        wr->eT[w][l] = n[0];
        wr->eB[w][l] = n[RPT - 1];
        if (w != 0) {                    // hT consumed as hD by warp w-1
            hm0 = hrow<BDRY>(n[0], l);
            wr->hT[w][l] = hm0;
        }
        if (w != NW - 1) {               // hB consumed as hU by warp w+1
            hm5 = hrow<BDRY>(n[RPT - 1], l);
            wr->hB[w][l] = hm5;
        }

        // ---- pairwise neighbor sync (lower barrier id first: no deadlock) ----
        if (w > 0)      BARP(w);
        if (w < NW - 1) BARP(w + 1);

        // ---- dilate (rolling vertical 3-max) + delta + sk: interior warps only ----
        if (w != 0 && w != NW - 1) {
            float4 hU = wr->hB[w - 1][l];
            float4 hD = wr->hT[w + 1][l];

            float4 hA = hU, hB = hm0;
#pragma unroll
            for (int r = 0; r < RPT; ++r) {
                float4 hC;
                if (r == RPT - 2)      hC = hm5;
                else if (r == RPT - 1) hC = hD;
                else                   hC = hrow<BDRY>(n[r + 1], l);

                float vx = fmaxf(hB.x, fmaxf(hA.x, hC.x));
                float vy = fmaxf(hB.y, fmaxf(hA.y, hC.y));
                float vz = fmaxf(hB.z, fmaxf(hA.z, hC.z));
                float vw = fmaxf(hB.w, fmaxf(hA.w, hC.w));

                float dx = fmaxf(e[r].x - vx, 0.f);
                float dy = fmaxf(e[r].y - vy, 0.f);
                float dz = fmaxf(e[r].z - vz, 0.f);
                float dw = fmaxf(e[r].w - vw, 0.f);

                // sk += d - sk*d  (relu dropped: argument >= -O(ulp), fma-pipe form)
                skr[r].x = __fmaf_rn(-skr[r].x, dx, skr[r].x + dx);
                skr[r].y = __fmaf_rn(-skr[r].y, dy, skr[r].y + dy);
                skr[r].z = __fmaf_rn(-skr[r].z, dz, skr[r].z + dz);
                skr[r].w = __fmaf_rn(-skr[r].w, dw, skr[r].w + dw);

                hA = hB; hB = hC;
                e[r] = n[r];
            }
        } else {
#pragma unroll
            for (int r = 0; r < RPT; ++r) e[r] = n[r];
        }
        // parity double-buffering + pairwise happens-before chain removes WAR hazards
    }
}

template<int NSTEPS>
__global__ void __launch_bounds__(NTH, 2)
skel_kernel(const float* __restrict__ img, float* __restrict__ sk,
            int insel, int outsel, int first)
{
    extern __shared__ Edges eb[];   // eb[2], 32 KB

    const float* ein  = (insel == 0) ? img : (insel == 1 ? g_e0 : g_e1);
    float*       eout = (outsel == 1) ? g_e0 : g_e1;

    const int b = blockIdx.z;
    int tx0 = blockIdx.x * INTW;
    if (tx0 > IMG - INTW) tx0 = IMG - INTW;     // clamped overlap tile (idempotent)
    const int ty0 = blockIdx.y * INTH;          // 32 x 32 = 1024 exact
    const int ocol = tx0 - 8, orow = ty0 - 8;

    const int t = threadIdx.x;
    const int l = t & 31, w = t >> 5;
    const int r0 = w * RPT;
    const int gc0 = ocol + 4 * l;

    const float* inb = ein  + (size_t)b * HWSZ;
    float*       skb = sk   + (size_t)b * HWSZ;
    float*       eob = eout + (size_t)b * HWSZ;

    const bool bdry = (orow < 0) | (orow + H > IMG) | (ocol < 0) | (ocol + W > IMG);

    // ---- load tile block into registers ----
    float4 e[RPT];
    if (!bdry) {
#pragma unroll
        for (int r = 0; r < RPT; ++r)
            e[r] = *(const float4*)(inb + (size_t)(orow + r0 + r) * IMG + gc0);
    } else {
#pragma unroll
        for (int r = 0; r < RPT; ++r) {
            int gr = orow + r0 + r;
            bool rok = (unsigned)gr < IMG;
            const float* row = inb + (size_t)(rok ? gr : 0) * IMG;
            float4 v;
            v.x = (rok && (unsigned)(gc0 + 0) < IMG) ? row[gc0 + 0] : SENT;
            v.y = (rok && (unsigned)(gc0 + 1) < IMG) ? row[gc0 + 1] : SENT;
            v.z = (rok && (unsigned)(gc0 + 2) < IMG) ? row[gc0 + 2] : SENT;
            v.w = (rok && (unsigned)(gc0 + 3) < IMG) ? row[gc0 + 3] : SENT;
            e[r] = v;
        }
    }

    // ---- sk accumulators (interior: lanes 2..29, rows 8..39) ----
    const bool xint = (l >= 2) && (l < 30);
    float4 skr[RPT];
#pragma unroll
    for (int r = 0; r < RPT; ++r) {
        int q = r0 + r;
        if (!first && xint && q >= 8 && q < 8 + INTH)
            skr[r] = *(const float4*)(skb + (size_t)(ty0 + q - 8) * IMG + (tx0 + 4 * (l - 2)));
        else
            skr[r] = make_float4(0.f, 0.f, 0.f, 0.f);
    }

    // ---- publish e_0 edges into parity 0 ----
    eb[0].eT[w][l] = e[0];
    eb[0].eB[w][l] = e[RPT - 1];
    __syncthreads();

    if (bdry) run_steps<true,  NSTEPS>(eb, e, skr, l, w, gc0, orow, r0);
    else      run_steps<false, NSTEPS>(eb, e, skr, l, w, gc0, orow, r0);

    // ---- write sk and final eroded image (interior 112x32) ----
    if (xint) {
#pragma unroll
        for (int r = 0; r < RPT; ++r) {
            int q = r0 + r;
            if (q >= 8 && q < 8 + INTH) {
                size_t g = (size_t)(ty0 + q - 8) * IMG + (tx0 + 4 * (l - 2));
                *(float4*)(skb + g) = skr[r];
                *(float4*)(eob + g) = e[r];
            }
        }
    }
}

extern "C" void kernel_launch(void* const* d_in, const int* in_sizes, int n_in,
                              void* d_out, int out_size)
{
    const float* img = (const float*)d_in[0];
    float* sk = (float*)d_out;

    const int smem = 2 * (int)sizeof(Edges);   // 32768 bytes
    cudaFuncSetAttribute(skel_kernel<7>,
                         cudaFuncAttributeMaxDynamicSharedMemorySize, smem);
    cudaFuncSetAttribute(skel_kernel<6>,
                         cudaFuncAttributeMaxDynamicSharedMemorySize, smem);

    dim3 grid((IMG + INTW - 1) / INTW, IMG / INTH, NB);  // 10 x 32 x 16
    dim3 block(NTH);

    // 6 launches: 7+7+7+7+7+6 = 41 deltas (e_0 .. e_41)
    skel_kernel<7><<<grid, block, smem>>>(img, sk, 0, 1, 1);
    skel_kernel<7><<<grid, block, smem>>>(img, sk, 1, 2, 0);
    skel_kernel<7><<<grid, block, smem>>>(img, sk, 2, 1, 0);
    skel_kernel<7><<<grid, block, smem>>>(img, sk, 1, 2, 0);
    skel_kernel<7><<<grid, block, smem>>>(img, sk, 2, 1, 0);
    skel_kernel<6><<<grid, block, smem>>>(img, sk, 1, 2, 0);
}